// round 13
// baseline (speedup 1.0000x reference)
#include <cuda_runtime.h>
#include <cuda_fp16.h>
#include <cstdint>
#include <math.h>

// JAX PRNG scheme: jax_threefry_partitionable=True (verified R2-R11)
#define NPIX   50176            // 224*224
#define IMG    150528           // 3*NPIX
#define BATCH  64
#define NUM_IT 64
#define TOTAL  (BATCH * IMG)
#define SIGMA_F 0.05f
#define NSEG   7                 // tile split: 7 segments
#define SEG_PAIRS 3584           // 25088 pairs / 7 = 3584 = 14 * 256 exactly

struct Keys { unsigned int k[2 * NUM_IT]; };

// Scratch (__device__ globals — sanctioned no-allocation path)
__device__ float g_logits_part[NSEG][(NUM_IT + 1) * BATCH];
__device__ float g_d[NUM_IT * BATCH];
__device__ float g_coef[BATCH];
__device__ float g_base[TOTAL];                       // imgs + noise, 38.5 MB
// Normalized noise as half2(ch0, ch1) per pixel; ch2 = -(ch0+ch1). 822 MB.
__device__ unsigned int g_tn_h[(size_t)NUM_IT * BATCH * NPIX];

typedef unsigned long long u64;

// ---------------------------------------------------------------------------
// f32x2 packed helpers (sm_10x)
// ---------------------------------------------------------------------------
__device__ __forceinline__ u64 pk2(float a, float b) {
    u64 r; asm("mov.b64 %0,{%1,%2};" : "=l"(r) : "f"(a), "f"(b)); return r;
}
__device__ __forceinline__ void upk2(u64 v, float &a, float &b) {
    asm("mov.b64 {%0,%1},%2;" : "=f"(a), "=f"(b) : "l"(v));
}
__device__ __forceinline__ u64 fma2(u64 a, u64 b, u64 c) {
    u64 r; asm("fma.rn.f32x2 %0,%1,%2,%3;" : "=l"(r) : "l"(a), "l"(b), "l"(c)); return r;
}
__device__ __forceinline__ u64 add2(u64 a, u64 b) {
    u64 r; asm("add.rn.f32x2 %0,%1,%2;" : "=l"(r) : "l"(a), "l"(b)); return r;
}
__device__ __forceinline__ u64 mul2(u64 a, u64 b) {
    u64 r; asm("mul.rn.f32x2 %0,%1,%2;" : "=l"(r) : "l"(a), "l"(b)); return r;
}
__device__ __forceinline__ u64 sp2(float a) { return pk2(a, a); }

// add with saturation to [0,1] in ONE FADD (fma pipe)
__device__ __forceinline__ float addsat(float a, float b) {
    float r; asm("add.rn.sat.f32 %0,%1,%2;" : "=f"(r) : "f"(a), "f"(b)); return r;
}
__device__ __forceinline__ float sat(float a) {
    float r; asm("add.rn.sat.f32 %0,%1,0f00000000;" : "=f"(r) : "f"(a)); return r;
}

// ---------------------------------------------------------------------------
// Host-side Threefry-2x32 (key derivation only)
// ---------------------------------------------------------------------------
static void tf2x32_host(unsigned int k0, unsigned int k1,
                        unsigned int x0, unsigned int x1,
                        unsigned int &o0, unsigned int &o1)
{
    unsigned int k2 = k0 ^ k1 ^ 0x1BD11BDAu;
    x0 += k0; x1 += k1;
#define TF_R(r) { x0 += x1; x1 = (x1 << (r)) | (x1 >> (32 - (r))); x1 ^= x0; }
    TF_R(13) TF_R(15) TF_R(26) TF_R(6)
    x0 += k1; x1 += k2 + 1u;
    TF_R(17) TF_R(29) TF_R(16) TF_R(24)
    x0 += k2; x1 += k0 + 2u;
    TF_R(13) TF_R(15) TF_R(26) TF_R(6)
    x0 += k0; x1 += k1 + 3u;
    TF_R(17) TF_R(29) TF_R(16) TF_R(24)
    x0 += k1; x1 += k2 + 4u;
    TF_R(13) TF_R(15) TF_R(26) TF_R(6)
    x0 += k2; x1 += k0 + 5u;
#undef TF_R
    o0 = x0; o1 = x1;
}

// ---------------------------------------------------------------------------
// Integer ops pinned to the fma pipe (IMAD/IMAD.HI) via opaque `one`
// ---------------------------------------------------------------------------
__device__ __forceinline__ unsigned int madd(unsigned int a, unsigned int one,
                                             unsigned int b)
{
    unsigned int r;
    asm("mad.lo.u32 %0, %1, %2, %3;" : "=r"(r) : "r"(a), "r"(one), "r"(b));
    return r;
}
__device__ __forceinline__ unsigned int madhi(unsigned int a, unsigned int b,
                                              unsigned int c)
{
    unsigned int r;
    asm("mad.hi.u32 %0, %1, %2, %3;" : "=r"(r) : "r"(a), "r"(b), "r"(c));
    return r;
}

// Threefry-2x32, counter (0, j), partitionable output x0^x1.
// R10 hash + ISOLATED IADD3 fusion: the 4 interior x0 key injections fuse
// with the following round-add into one IADD3 (issue -4/el, alu +4/el).
__device__ __forceinline__ unsigned int rbits_m(
    unsigned int k0, unsigned int k1, unsigned int k2,
    unsigned int j, unsigned int one)
{
#define ROTX(r) { x1 = (x1 << (r)) | (x1 >> (32 - (r))); x1 ^= x0; }
#define TF_RM(r) { x0 = madd(x1, one, x0); ROTX(r) }
    unsigned int x0 = k0;                    // counter hi = 0
    unsigned int x1 = madd(j, one, k1);      // counter lo = j
    TF_RM(13) TF_RM(15) TF_RM(26) TF_RM(6)
    x1 = madd(x1, one, k2 + 1u);
    x0 = x0 + k1 + x1;  ROTX(17)             // IADD3: inj + round add
    TF_RM(29) TF_RM(16) TF_RM(24)
    x1 = madd(x1, one, k0 + 2u);
    x0 = x0 + k2 + x1;  ROTX(13)
    TF_RM(15) TF_RM(26) TF_RM(6)
    x1 = madd(x1, one, k1 + 3u);
    x0 = x0 + k0 + x1;  ROTX(17)
    TF_RM(29) TF_RM(16) TF_RM(24)
    x1 = madd(x1, one, k2 + 4u);
    x0 = x0 + k1 + x1;  ROTX(13)
    TF_RM(15) TF_RM(26) TF_RM(6)
    x1 = madd(x1, one, k0 + 5u);
    x0 = madd(x0, one, k2);
    return x0 ^ x1;
#undef TF_RM
#undef ROTX
}

// Tail fixup (w >= 5): XLA's Giles tail polynomial, scalar, inline, rare.
__device__ __forceinline__ float tail_fix(float w, float x)
{
    float s = sqrtf(w) - 3.0f;
    float p =          -0.000200214257f;
    p = fmaf(p, s, 0.000100950558f);
    p = fmaf(p, s, 0.00134934322f);
    p = fmaf(p, s, -0.00367342844f);
    p = fmaf(p, s, 0.00573950773f);
    p = fmaf(p, s, -0.0076224613f);
    p = fmaf(p, s, 0.00943887047f);
    p = fmaf(p, s, 1.00167406f);
    p = fmaf(p, s, 2.83297682f);
    return p * x;
}

// Packed normals (erfinv/sqrt2-scaled); ln2 scale and -2.5 shift folded into
// transformed Giles coefficients, Horner variable zz = log2(1-u^2) + 2.5/ln2.
__device__ __forceinline__ u64 normal2(unsigned int ba, unsigned int bb)
{
    // (bits>>9)|0x3f800000 == mad.hi(bits, 1<<23, 0x3f800000)  (fma pipe)
    unsigned int ia = madhi(ba, 0x00800000u, 0x3f800000u);
    unsigned int ib = madhi(bb, 0x00800000u, 0x3f800000u);
    u64 v = pk2(__uint_as_float(ia), __uint_as_float(ib));
    u64 f = add2(v, sp2(-1.0f));                       // exact (Sterbenz)
    u64 u = fma2(f, sp2(2.0f), sp2(-0.99999994f));     // uniform in [lo,1)
    u64 s = fma2(u, u, sp2(-1.0f));                    // u^2-1 = -(1-u^2)
    float sa_, sb_; upk2(s, sa_, sb_);
    float za = __log2f(-sa_);                          // log2(1-u^2) <= 0
    float zb = __log2f(-sb_);
    u64 zz = add2(pk2(za, zb), sp2(3.6067376f));       // + 2.5/ln2

    u64 p = sp2(1.49742e-9f);                          // e8
    p = fma2(p, zz, sp2(-2.63893e-8f));                // e7
    p = fma2(p, zz, sp2(-3.90762e-7f));                // e6
    p = fma2(p, zz, sp2(7.02653e-7f));                 // e5
    p = fma2(p, zz, sp2(5.045614e-5f));                // e4
    p = fma2(p, zz, sp2(4.1752126e-4f));               // e3
    p = fma2(p, zz, sp2(-2.00718e-3f));                // e2
    p = fma2(p, zz, sp2(-0.17095832f));                // e1
    p = fma2(p, zz, sp2(1.50140941f));                 // e0
    u64 r = mul2(p, u);

    float zza, zzb; upk2(zz, zza, zzb);
    if (zza <= -3.6067376f || zzb <= -3.6067376f) {    // ~20% warp trigger
        float ra, rb, ua_, ub_;
        upk2(r, ra, rb); upk2(u, ua_, ub_);
        if (zza <= -3.6067376f)
            ra = tail_fix(fmaf(-0.6931472f, zza, 2.5f), ua_);
        if (zzb <= -3.6067376f)
            rb = tail_fix(fmaf(-0.6931472f, zzb, 2.5f), ub_);
        r = pk2(ra, rb);
    }
    return r;
}

// ---------------------------------------------------------------------------
// K0: g_base = imgs + noise (iteration-invariant; hoisted out of K1)
// ---------------------------------------------------------------------------
__global__ void __launch_bounds__(256) k_base(
    const float* __restrict__ imgs, const float* __restrict__ noise)
{
    int i = blockIdx.x * 256 + threadIdx.x;      // TOTAL/4 float4s
    float4 a = reinterpret_cast<const float4*>(imgs)[i];
    float4 n = reinterpret_cast<const float4*>(noise)[i];
    a.x += n.x; a.y += n.y; a.z += n.z; a.w += n.w;
    reinterpret_cast<float4*>(g_base)[i] = a;
}

// ---------------------------------------------------------------------------
// K1: grid (NSEG, BATCH, NUM_IT+1). Each block: one 1/7 pixel segment of one
// (iter, image) tile: exactly 14 loop iters (3584 pairs = 14*256).
// (R10 structure — the R11 quad/ILP restructure regressed and is reverted.)
// ---------------------------------------------------------------------------
__global__ void __launch_bounds__(256, 8) k_logits(
    const float* __restrict__ w, Keys keys, unsigned int one)
{
    const int seg = blockIdx.x;          // pixel segment: 0..6
    const int b   = blockIdx.y;
    const int it  = blockIdx.z;
    const int tid = threadIdx.x;
    const int base = b * IMG;
    const int qbeg = seg * SEG_PAIRS + tid;
    const int qend = (seg + 1) * SEG_PAIRS;

    float acc = 0.0f;
    if (it < NUM_IT) {
        const unsigned int k0 = keys.k[2 * it], k1 = keys.k[2 * it + 1];
        const unsigned int k2 = k0 ^ k1 ^ 0x1BD11BDAu;
        unsigned int* __restrict__ tdst = g_tn_h + ((size_t)it * BATCH + b) * NPIX;
        #pragma unroll 1
        for (int q = qbeg; q < qend; q += 256) {
            const int p  = 2 * q;
            const int j0 = base + p;
            // 6 hashes: 2 pixels x 3 channels
            u64 t0 = normal2(rbits_m(k0,k1,k2,(unsigned)j0,           one),
                             rbits_m(k0,k1,k2,(unsigned)(j0+1),       one));
            u64 t1 = normal2(rbits_m(k0,k1,k2,(unsigned)(j0+NPIX),    one),
                             rbits_m(k0,k1,k2,(unsigned)(j0+NPIX+1),  one));
            u64 t2 = normal2(rbits_m(k0,k1,k2,(unsigned)(j0+2*NPIX),  one),
                             rbits_m(k0,k1,k2,(unsigned)(j0+2*NPIX+1),one));
            // channel normalization, packed across the pixel pair
            u64 sum   = add2(add2(t0, t1), t2);
            u64 negmu = mul2(sum, sp2(-1.0f / 3.0f));
            u64 d0 = add2(t0, negmu), d1 = add2(t1, negmu), d2 = add2(t2, negmu);
            u64 var = mul2(d0, d0);
            var = fma2(d1, d1, var);
            var = fma2(d2, d2, var);                   // = 2 * var(ddof=1)
            // sc = sigma*sqrt(2)/sqrt(2var) = rsqrt(2var * 200)
            u64 varK = mul2(var, sp2(200.0f));
            float va_, vb_; upk2(varK, va_, vb_);
            u64 sc = pk2(rsqrtf(va_), rsqrtf(vb_));
            u64 tn0 = mul2(d0, sc), tn1 = mul2(d1, sc), tn2 = mul2(d2, sc);

            // store half2(ch0, ch1) per pixel as one STG.64 for the pair
            float x0a, x0b, x1a, x1b;
            upk2(tn0, x0a, x0b); upk2(tn1, x1a, x1b);
            __half2 hA = __floats2half2_rn(x0a, x1a);
            __half2 hB = __floats2half2_rn(x0b, x1b);
            uint2 st;
            st.x = *reinterpret_cast<unsigned int*>(&hA);
            st.y = *reinterpret_cast<unsigned int*>(&hB);
            *reinterpret_cast<uint2*>(tdst + p) = st;

            // dot: clip folded into FADD.SAT, base preadded
            float x2a, x2b; upk2(tn2, x2a, x2b);
            const float2 b0 = *reinterpret_cast<const float2*>(g_base + j0);
            const float2 b1 = *reinterpret_cast<const float2*>(g_base + j0 + NPIX);
            const float2 b2 = *reinterpret_cast<const float2*>(g_base + j0 + 2*NPIX);
            const float2 w0 = *reinterpret_cast<const float2*>(w + p);
            const float2 w1 = *reinterpret_cast<const float2*>(w + p + NPIX);
            const float2 w2 = *reinterpret_cast<const float2*>(w + p + 2*NPIX);
            acc = fmaf(addsat(b0.x, x0a), w0.x, acc);
            acc = fmaf(addsat(b0.y, x0b), w0.y, acc);
            acc = fmaf(addsat(b1.x, x1a), w1.x, acc);
            acc = fmaf(addsat(b1.y, x1b), w1.y, acc);
            acc = fmaf(addsat(b2.x, x2a), w2.x, acc);
            acc = fmaf(addsat(b2.y, x2b), w2.y, acc);
        }
    } else {
        #pragma unroll 1
        for (int q = qbeg; q < qend; q += 256) {
            const int p  = 2 * q;
            const int j0 = base + p;
            const float2 b0 = *reinterpret_cast<const float2*>(g_base + j0);
            const float2 b1 = *reinterpret_cast<const float2*>(g_base + j0 + NPIX);
            const float2 b2 = *reinterpret_cast<const float2*>(g_base + j0 + 2*NPIX);
            const float2 w0 = *reinterpret_cast<const float2*>(w + p);
            const float2 w1 = *reinterpret_cast<const float2*>(w + p + NPIX);
            const float2 w2 = *reinterpret_cast<const float2*>(w + p + 2*NPIX);
            acc = fmaf(sat(b0.x), w0.x, acc);
            acc = fmaf(sat(b0.y), w0.y, acc);
            acc = fmaf(sat(b1.x), w1.x, acc);
            acc = fmaf(sat(b1.y), w1.y, acc);
            acc = fmaf(sat(b2.x), w2.x, acc);
            acc = fmaf(sat(b2.y), w2.y, acc);
        }
    }

    __shared__ float red[256];
    red[tid] = acc;
    __syncthreads();
    #pragma unroll
    for (int s = 128; s > 32; s >>= 1) {
        if (tid < s) red[tid] += red[tid + s];
        __syncthreads();
    }
    if (tid < 32) {
        float v = red[tid] + red[tid + 32];
        #pragma unroll
        for (int o = 16; o > 0; o >>= 1)
            v += __shfl_down_sync(0xFFFFFFFFu, v, o);
        if (tid == 0) g_logits_part[seg][it * BATCH + b] = v;
    }
}

// ---------------------------------------------------------------------------
// K2: per-image d_i, nc, coef (sums the NSEG partial logits, fixed order)
// ---------------------------------------------------------------------------
__global__ void k_dvals(const float* __restrict__ b_dnet)
{
    int b = threadIdx.x;
    if (b >= BATCH) return;
    float bb = b_dnet[0];
    float l2 = 0.0f;
    #pragma unroll
    for (int s = 0; s < NSEG; s++) l2 += g_logits_part[s][NUM_IT * BATCH + b];
    float p2 = 1.0f / (1.0f + expf(-(l2 + bb)));
    float nc = 0.0f;
    #pragma unroll 1
    for (int i = 0; i < NUM_IT; i++) {
        float li = 0.0f;
        #pragma unroll
        for (int s = 0; s < NSEG; s++) li += g_logits_part[s][i * BATCH + b];
        float pi = 1.0f / (1.0f + expf(-(li + bb)));
        float d = p2 - pi;
        g_d[i * BATCH + b] = d;
        nc = fmaf(d, d, nc);
    }
    g_coef[b] = 1.0f / ((float)NUM_IT * (sqrtf(nc) + 1e-10f) * SIGMA_F);
}

// ---------------------------------------------------------------------------
// K3: per-pixel output; stream precomputed half2 tn (822 MB read, DRAM-bound)
// ---------------------------------------------------------------------------
__global__ void __launch_bounds__(256) k_output(float* __restrict__ out)
{
    __shared__ float dsh[NUM_IT];
    const int b = blockIdx.y;
    if (threadIdx.x < NUM_IT) dsh[threadIdx.x] = g_d[threadIdx.x * BATCH + b];
    __syncthreads();

    const int p = blockIdx.x * 256 + threadIdx.x;
    const size_t stride = (size_t)BATCH * NPIX;
    const unsigned int* __restrict__ tp = g_tn_h + (size_t)b * NPIX + p;

    float a0 = 0.0f, a1 = 0.0f, a2 = 0.0f;
    #pragma unroll 8
    for (int i = 0; i < NUM_IT; i++) {
        unsigned int hb = tp[i * stride];
        __half2 h = *reinterpret_cast<__half2*>(&hb);
        float2 tn = __half22float2(h);
        float di = dsh[i];
        a0 = fmaf(tn.x, di, a0);
        a1 = fmaf(tn.y, di, a1);
        a2 = fmaf(-(tn.x + tn.y), di, a2);
    }
    float c = g_coef[b];
    const int j0 = b * IMG + p;
    out[j0]            = a0 * c;
    out[j0 + NPIX]     = a1 * c;
    out[j0 + 2 * NPIX] = a2 * c;
}

// ---------------------------------------------------------------------------
extern "C" void kernel_launch(void* const* d_in, const int* in_sizes, int n_in,
                              void* d_out, int out_size)
{
    const float* imgs  = (const float*)d_in[0];
    const float* noise = (const float*)d_in[1];
    const float* w     = (const float*)d_in[2];
    const float* bb    = (const float*)d_in[3];
    float* out = (float*)d_out;

    // keys = jax.random.split(jax.random.key(42), 64); base key data (0, 42)
    Keys keys;
    for (int i = 0; i < NUM_IT; i++) {
        unsigned int o0, o1;
        tf2x32_host(0u, 42u, 0u, (unsigned)i, o0, o1);
        keys.k[2 * i] = o0; keys.k[2 * i + 1] = o1;
    }

    k_base<<<TOTAL / 4 / 256, 256>>>(imgs, noise);

    dim3 g1(NSEG, BATCH, NUM_IT + 1);   // 7 x 64 x 65 = 29120 blocks
    k_logits<<<g1, 256>>>(w, keys, 1u);

    k_dvals<<<1, 64>>>(bb);

    dim3 g3(NPIX / 256, BATCH);   // 50176 = 196 * 256 exactly
    k_output<<<g3, 256>>>(out);
}

// round 15
// speedup vs baseline: 1.0476x; 1.0476x over previous
#include <cuda_runtime.h>
#include <cuda_fp16.h>
#include <cstdint>
#include <math.h>

// JAX PRNG scheme: jax_threefry_partitionable=True (verified R2-R12)
#define NPIX   50176            // 224*224
#define IMG    150528           // 3*NPIX
#define BATCH  64
#define NUM_IT 64
#define TOTAL  (BATCH * IMG)
#define NPAIRS 25088            // NPIX/2
#define SIGMA_F 0.05f
#define NSEG   7                 // tile split: 7 segments
#define SEG_PAIRS 3584           // 25088 / 7 = 3584 = 14 * 256 exactly

struct Keys { unsigned int k[2 * NUM_IT]; };

// Scratch (__device__ globals — sanctioned no-allocation path)
__device__ float g_logits_part[NSEG][(NUM_IT + 1) * BATCH];
__device__ float g_d[NUM_IT * BATCH];
__device__ float g_coef[BATCH];
// Interleaved per-pair operands: 8 floats {b0x,b0y,b1x,b1y,b2x,b2y,0,0}
__device__ float4 g_bt[(size_t)BATCH * NPAIRS * 2];   // 51.4 MB
__device__ float4 g_wt[(size_t)NPAIRS * 2];           // 0.8 MB
// Normalized noise as half2(ch0, ch1) per pixel; ch2 = -(ch0+ch1). 822 MB.
__device__ unsigned int g_tn_h[(size_t)NUM_IT * BATCH * NPIX];

typedef unsigned long long u64;

// ---------------------------------------------------------------------------
// f32x2 packed helpers (sm_10x)
// ---------------------------------------------------------------------------
__device__ __forceinline__ u64 pk2(float a, float b) {
    u64 r; asm("mov.b64 %0,{%1,%2};" : "=l"(r) : "f"(a), "f"(b)); return r;
}
__device__ __forceinline__ void upk2(u64 v, float &a, float &b) {
    asm("mov.b64 {%0,%1},%2;" : "=f"(a), "=f"(b) : "l"(v));
}
__device__ __forceinline__ u64 fma2(u64 a, u64 b, u64 c) {
    u64 r; asm("fma.rn.f32x2 %0,%1,%2,%3;" : "=l"(r) : "l"(a), "l"(b), "l"(c)); return r;
}
__device__ __forceinline__ u64 add2(u64 a, u64 b) {
    u64 r; asm("add.rn.f32x2 %0,%1,%2;" : "=l"(r) : "l"(a), "l"(b)); return r;
}
__device__ __forceinline__ u64 mul2(u64 a, u64 b) {
    u64 r; asm("mul.rn.f32x2 %0,%1,%2;" : "=l"(r) : "l"(a), "l"(b)); return r;
}
__device__ __forceinline__ u64 sp2(float a) { return pk2(a, a); }

// scalar add with saturation to [0,1] in ONE FADD (fma pipe)
__device__ __forceinline__ float addsat(float a, float b) {
    float r; asm("add.rn.sat.f32 %0,%1,%2;" : "=f"(r) : "f"(a), "f"(b)); return r;
}
__device__ __forceinline__ float sat(float a) {
    float r; asm("add.rn.sat.f32 %0,%1,0f00000000;" : "=f"(r) : "f"(a)); return r;
}

// ---------------------------------------------------------------------------
// Host-side Threefry-2x32 (key derivation only)
// ---------------------------------------------------------------------------
static void tf2x32_host(unsigned int k0, unsigned int k1,
                        unsigned int x0, unsigned int x1,
                        unsigned int &o0, unsigned int &o1)
{
    unsigned int k2 = k0 ^ k1 ^ 0x1BD11BDAu;
    x0 += k0; x1 += k1;
#define TF_R(r) { x0 += x1; x1 = (x1 << (r)) | (x1 >> (32 - (r))); x1 ^= x0; }
    TF_R(13) TF_R(15) TF_R(26) TF_R(6)
    x0 += k1; x1 += k2 + 1u;
    TF_R(17) TF_R(29) TF_R(16) TF_R(24)
    x0 += k2; x1 += k0 + 2u;
    TF_R(13) TF_R(15) TF_R(26) TF_R(6)
    x0 += k0; x1 += k1 + 3u;
    TF_R(17) TF_R(29) TF_R(16) TF_R(24)
    x0 += k1; x1 += k2 + 4u;
    TF_R(13) TF_R(15) TF_R(26) TF_R(6)
    x0 += k2; x1 += k0 + 5u;
#undef TF_R
    o0 = x0; o1 = x1;
}

// ---------------------------------------------------------------------------
// Integer ops pinned to the fma pipe (IMAD/IMAD.HI) via opaque `one`
// ---------------------------------------------------------------------------
__device__ __forceinline__ unsigned int madd(unsigned int a, unsigned int one,
                                             unsigned int b)
{
    unsigned int r;
    asm("mad.lo.u32 %0, %1, %2, %3;" : "=r"(r) : "r"(a), "r"(one), "r"(b));
    return r;
}
__device__ __forceinline__ unsigned int madhi(unsigned int a, unsigned int b,
                                              unsigned int c)
{
    unsigned int r;
    asm("mad.hi.u32 %0, %1, %2, %3;" : "=r"(r) : "r"(a), "r"(b), "r"(c));
    return r;
}

// Threefry-2x32, counter (0, j), partitionable output x0^x1.  (R10 exact.)
__device__ __forceinline__ unsigned int rbits_m(
    unsigned int k0, unsigned int k1, unsigned int k2,
    unsigned int j, unsigned int one)
{
    unsigned int x0 = k0;                    // counter hi = 0
    unsigned int x1 = madd(j, one, k1);      // counter lo = j
#define TF_RM(r) { x0 = madd(x1, one, x0); \
                   x1 = (x1 << (r)) | (x1 >> (32 - (r))); x1 ^= x0; }
    TF_RM(13) TF_RM(15) TF_RM(26) TF_RM(6)
    x0 = madd(x0, one, k1); x1 = madd(x1, one, k2 + 1u);
    TF_RM(17) TF_RM(29) TF_RM(16) TF_RM(24)
    x0 = madd(x0, one, k2); x1 = madd(x1, one, k0 + 2u);
    TF_RM(13) TF_RM(15) TF_RM(26) TF_RM(6)
    x0 = madd(x0, one, k0); x1 = madd(x1, one, k1 + 3u);
    TF_RM(17) TF_RM(29) TF_RM(16) TF_RM(24)
    x0 = madd(x0, one, k1); x1 = madd(x1, one, k2 + 4u);
    TF_RM(13) TF_RM(15) TF_RM(26) TF_RM(6)
    x0 = madd(x0, one, k2); x1 = madd(x1, one, k0 + 5u);
#undef TF_RM
    return x0 ^ x1;
}

// Tail fixup (w >= 5): XLA's Giles tail polynomial, scalar, inline, rare.
__device__ __forceinline__ float tail_fix(float w, float x)
{
    float s = sqrtf(w) - 3.0f;
    float p =          -0.000200214257f;
    p = fmaf(p, s, 0.000100950558f);
    p = fmaf(p, s, 0.00134934322f);
    p = fmaf(p, s, -0.00367342844f);
    p = fmaf(p, s, 0.00573950773f);
    p = fmaf(p, s, -0.0076224613f);
    p = fmaf(p, s, 0.00943887047f);
    p = fmaf(p, s, 1.00167406f);
    p = fmaf(p, s, 2.83297682f);
    return p * x;
}

// Packed normals (erfinv/sqrt2-scaled); ln2 scale and -2.5 shift folded into
// transformed Giles coefficients, Horner variable zz = log2(1-u^2) + 2.5/ln2.
__device__ __forceinline__ u64 normal2(unsigned int ba, unsigned int bb)
{
    // (bits>>9)|0x3f800000 == mad.hi(bits, 1<<23, 0x3f800000)  (fma pipe)
    unsigned int ia = madhi(ba, 0x00800000u, 0x3f800000u);
    unsigned int ib = madhi(bb, 0x00800000u, 0x3f800000u);
    u64 v = pk2(__uint_as_float(ia), __uint_as_float(ib));
    u64 f = add2(v, sp2(-1.0f));                       // exact (Sterbenz)
    u64 u = fma2(f, sp2(2.0f), sp2(-0.99999994f));     // uniform in [lo,1)
    u64 s = fma2(u, u, sp2(-1.0f));                    // u^2-1 = -(1-u^2)
    float sa_, sb_; upk2(s, sa_, sb_);
    float za = __log2f(-sa_);                          // log2(1-u^2) <= 0
    float zb = __log2f(-sb_);
    u64 zz = add2(pk2(za, zb), sp2(3.6067376f));       // + 2.5/ln2

    u64 p = sp2(1.49742e-9f);                          // e8
    p = fma2(p, zz, sp2(-2.63893e-8f));                // e7
    p = fma2(p, zz, sp2(-3.90762e-7f));                // e6
    p = fma2(p, zz, sp2(7.02653e-7f));                 // e5
    p = fma2(p, zz, sp2(5.045614e-5f));                // e4
    p = fma2(p, zz, sp2(4.1752126e-4f));               // e3
    p = fma2(p, zz, sp2(-2.00718e-3f));                // e2
    p = fma2(p, zz, sp2(-0.17095832f));                // e1
    p = fma2(p, zz, sp2(1.50140941f));                 // e0
    u64 r = mul2(p, u);

    float zza, zzb; upk2(zz, zza, zzb);
    if (zza <= -3.6067376f || zzb <= -3.6067376f) {    // ~20% warp trigger
        float ra, rb, ua_, ub_;
        upk2(r, ra, rb); upk2(u, ua_, ub_);
        if (zza <= -3.6067376f)
            ra = tail_fix(fmaf(-0.6931472f, zza, 2.5f), ua_);
        if (zzb <= -3.6067376f)
            rb = tail_fix(fmaf(-0.6931472f, zzb, 2.5f), ub_);
        r = pk2(ra, rb);
    }
    return r;
}

// ---------------------------------------------------------------------------
// K0a: build interleaved per-pair base records (imgs + noise, transposed)
// One thread per pair per image: reads 6 scalars, writes 32 B.
// ---------------------------------------------------------------------------
__global__ void __launch_bounds__(256) k_base(
    const float* __restrict__ imgs, const float* __restrict__ noise)
{
    int idx = blockIdx.x * 256 + threadIdx.x;        // 64*25088 = 1605632
    int b = idx / NPAIRS;
    int q = idx - b * NPAIRS;
    int j0 = b * IMG + 2 * q;
    float4 lo, hi;
    lo.x = imgs[j0]            + noise[j0];
    lo.y = imgs[j0 + 1]        + noise[j0 + 1];
    lo.z = imgs[j0 + NPIX]     + noise[j0 + NPIX];
    lo.w = imgs[j0 + NPIX + 1] + noise[j0 + NPIX + 1];
    hi.x = imgs[j0 + 2*NPIX]     + noise[j0 + 2*NPIX];
    hi.y = imgs[j0 + 2*NPIX + 1] + noise[j0 + 2*NPIX + 1];
    hi.z = 0.0f; hi.w = 0.0f;
    g_bt[(size_t)idx * 2]     = lo;
    g_bt[(size_t)idx * 2 + 1] = hi;
}

// K0b: same interleave for w (pair-major, batch-independent)
__global__ void __launch_bounds__(256) k_wt(const float* __restrict__ w)
{
    int q = blockIdx.x * 256 + threadIdx.x;          // 25088
    int p = 2 * q;
    float4 lo, hi;
    lo.x = w[p];            lo.y = w[p + 1];
    lo.z = w[p + NPIX];     lo.w = w[p + NPIX + 1];
    hi.x = w[p + 2*NPIX];   hi.y = w[p + 2*NPIX + 1];
    hi.z = 0.0f; hi.w = 0.0f;
    g_wt[(size_t)q * 2]     = lo;
    g_wt[(size_t)q * 2 + 1] = hi;
}

// ---------------------------------------------------------------------------
// K1: grid (NSEG, BATCH, NUM_IT+1). Each block: one 1/7 pixel segment of one
// (iter, image) tile: exactly 14 loop iters (3584 pairs = 14*256).
// Operand loads are 4x LDG.128 per pair (interleaved records) vs 6x LDG.64.
// ---------------------------------------------------------------------------
__global__ void __launch_bounds__(256, 8) k_logits(Keys keys, unsigned int one)
{
    const int seg = blockIdx.x;          // pixel segment: 0..6
    const int b   = blockIdx.y;
    const int it  = blockIdx.z;
    const int tid = threadIdx.x;
    const int base = b * IMG;
    const int qbeg = seg * SEG_PAIRS + tid;
    const int qend = (seg + 1) * SEG_PAIRS;
    const float4* __restrict__ btp = g_bt + (size_t)b * NPAIRS * 2;

    float acc = 0.0f;
    if (it < NUM_IT) {
        const unsigned int k0 = keys.k[2 * it], k1 = keys.k[2 * it + 1];
        const unsigned int k2 = k0 ^ k1 ^ 0x1BD11BDAu;
        unsigned int* __restrict__ tdst = g_tn_h + ((size_t)it * BATCH + b) * NPIX;
        #pragma unroll 1
        for (int q = qbeg; q < qend; q += 256) {
            const int p  = 2 * q;
            const int j0 = base + p;
            // 6 hashes: 2 pixels x 3 channels
            u64 t0 = normal2(rbits_m(k0,k1,k2,(unsigned)j0,           one),
                             rbits_m(k0,k1,k2,(unsigned)(j0+1),       one));
            u64 t1 = normal2(rbits_m(k0,k1,k2,(unsigned)(j0+NPIX),    one),
                             rbits_m(k0,k1,k2,(unsigned)(j0+NPIX+1),  one));
            u64 t2 = normal2(rbits_m(k0,k1,k2,(unsigned)(j0+2*NPIX),  one),
                             rbits_m(k0,k1,k2,(unsigned)(j0+2*NPIX+1),one));
            // channel normalization, packed across the pixel pair
            u64 sum   = add2(add2(t0, t1), t2);
            u64 negmu = mul2(sum, sp2(-1.0f / 3.0f));
            u64 d0 = add2(t0, negmu), d1 = add2(t1, negmu), d2 = add2(t2, negmu);
            u64 var = mul2(d0, d0);
            var = fma2(d1, d1, var);
            var = fma2(d2, d2, var);                   // = 2 * var(ddof=1)
            // sc = sigma*sqrt(2)/sqrt(2var) = rsqrt(2var * 200)
            u64 varK = mul2(var, sp2(200.0f));
            float va_, vb_; upk2(varK, va_, vb_);
            u64 sc = pk2(rsqrtf(va_), rsqrtf(vb_));
            u64 tn0 = mul2(d0, sc), tn1 = mul2(d1, sc), tn2 = mul2(d2, sc);

            // store half2(ch0, ch1) per pixel as one STG.64 for the pair
            float x0a, x0b, x1a, x1b;
            upk2(tn0, x0a, x0b); upk2(tn1, x1a, x1b);
            __half2 hA = __floats2half2_rn(x0a, x1a);
            __half2 hB = __floats2half2_rn(x0b, x1b);
            uint2 st;
            st.x = *reinterpret_cast<unsigned int*>(&hA);
            st.y = *reinterpret_cast<unsigned int*>(&hB);
            *reinterpret_cast<uint2*>(tdst + p) = st;

            // dot: 4x LDG.128 interleaved operands, clip folded into FADD.SAT
            float x2a, x2b; upk2(tn2, x2a, x2b);
            const float4 bl = btp[(size_t)q * 2];
            const float4 bh = btp[(size_t)q * 2 + 1];
            const float4 wl = g_wt[(size_t)q * 2];
            const float4 wh = g_wt[(size_t)q * 2 + 1];
            acc = fmaf(addsat(bl.x, x0a), wl.x, acc);
            acc = fmaf(addsat(bl.y, x0b), wl.y, acc);
            acc = fmaf(addsat(bl.z, x1a), wl.z, acc);
            acc = fmaf(addsat(bl.w, x1b), wl.w, acc);
            acc = fmaf(addsat(bh.x, x2a), wh.x, acc);
            acc = fmaf(addsat(bh.y, x2b), wh.y, acc);
        }
    } else {
        #pragma unroll 1
        for (int q = qbeg; q < qend; q += 256) {
            const float4 bl = btp[(size_t)q * 2];
            const float4 bh = btp[(size_t)q * 2 + 1];
            const float4 wl = g_wt[(size_t)q * 2];
            const float4 wh = g_wt[(size_t)q * 2 + 1];
            acc = fmaf(sat(bl.x), wl.x, acc);
            acc = fmaf(sat(bl.y), wl.y, acc);
            acc = fmaf(sat(bl.z), wl.z, acc);
            acc = fmaf(sat(bl.w), wl.w, acc);
            acc = fmaf(sat(bh.x), wh.x, acc);
            acc = fmaf(sat(bh.y), wh.y, acc);
        }
    }

    __shared__ float red[256];
    red[tid] = acc;
    __syncthreads();
    #pragma unroll
    for (int s = 128; s > 32; s >>= 1) {
        if (tid < s) red[tid] += red[tid + s];
        __syncthreads();
    }
    if (tid < 32) {
        float v = red[tid] + red[tid + 32];
        #pragma unroll
        for (int o = 16; o > 0; o >>= 1)
            v += __shfl_down_sync(0xFFFFFFFFu, v, o);
        if (tid == 0) g_logits_part[seg][it * BATCH + b] = v;
    }
}

// ---------------------------------------------------------------------------
// K2: per-image d_i, nc, coef (sums the NSEG partial logits, fixed order)
// ---------------------------------------------------------------------------
__global__ void k_dvals(const float* __restrict__ b_dnet)
{
    int b = threadIdx.x;
    if (b >= BATCH) return;
    float bb = b_dnet[0];
    float l2 = 0.0f;
    #pragma unroll
    for (int s = 0; s < NSEG; s++) l2 += g_logits_part[s][NUM_IT * BATCH + b];
    float p2 = 1.0f / (1.0f + expf(-(l2 + bb)));
    float nc = 0.0f;
    #pragma unroll 1
    for (int i = 0; i < NUM_IT; i++) {
        float li = 0.0f;
        #pragma unroll
        for (int s = 0; s < NSEG; s++) li += g_logits_part[s][i * BATCH + b];
        float pi = 1.0f / (1.0f + expf(-(li + bb)));
        float d = p2 - pi;
        g_d[i * BATCH + b] = d;
        nc = fmaf(d, d, nc);
    }
    g_coef[b] = 1.0f / ((float)NUM_IT * (sqrtf(nc) + 1e-10f) * SIGMA_F);
}

// ---------------------------------------------------------------------------
// K3: per-pixel output; stream precomputed half2 tn (822 MB read, DRAM-bound)
// ---------------------------------------------------------------------------
__global__ void __launch_bounds__(256) k_output(float* __restrict__ out)
{
    __shared__ float dsh[NUM_IT];
    const int b = blockIdx.y;
    if (threadIdx.x < NUM_IT) dsh[threadIdx.x] = g_d[threadIdx.x * BATCH + b];
    __syncthreads();

    const int p = blockIdx.x * 256 + threadIdx.x;
    const size_t stride = (size_t)BATCH * NPIX;
    const unsigned int* __restrict__ tp = g_tn_h + (size_t)b * NPIX + p;

    float a0 = 0.0f, a1 = 0.0f, a2 = 0.0f;
    #pragma unroll 8
    for (int i = 0; i < NUM_IT; i++) {
        unsigned int hb = tp[i * stride];
        __half2 h = *reinterpret_cast<__half2*>(&hb);
        float2 tn = __half22float2(h);
        float di = dsh[i];
        a0 = fmaf(tn.x, di, a0);
        a1 = fmaf(tn.y, di, a1);
        a2 = fmaf(-(tn.x + tn.y), di, a2);
    }
    float c = g_coef[b];
    const int j0 = b * IMG + p;
    out[j0]            = a0 * c;
    out[j0 + NPIX]     = a1 * c;
    out[j0 + 2 * NPIX] = a2 * c;
}

// ---------------------------------------------------------------------------
extern "C" void kernel_launch(void* const* d_in, const int* in_sizes, int n_in,
                              void* d_out, int out_size)
{
    const float* imgs  = (const float*)d_in[0];
    const float* noise = (const float*)d_in[1];
    const float* w     = (const float*)d_in[2];
    const float* bb    = (const float*)d_in[3];
    float* out = (float*)d_out;

    // keys = jax.random.split(jax.random.key(42), 64); base key data (0, 42)
    Keys keys;
    for (int i = 0; i < NUM_IT; i++) {
        unsigned int o0, o1;
        tf2x32_host(0u, 42u, 0u, (unsigned)i, o0, o1);
        keys.k[2 * i] = o0; keys.k[2 * i + 1] = o1;
    }

    k_base<<<(BATCH * NPAIRS) / 256, 256>>>(imgs, noise);  // 6272 blocks
    k_wt<<<NPAIRS / 256, 256>>>(w);                        // 98 blocks

    dim3 g1(NSEG, BATCH, NUM_IT + 1);   // 7 x 64 x 65 = 29120 blocks
    k_logits<<<g1, 256>>>(keys, 1u);

    k_dvals<<<1, 64>>>(bb);

    dim3 g3(NPIX / 256, BATCH);   // 50176 = 196 * 256 exactly
    k_output<<<g3, 256>>>(out);
}

// round 16
// speedup vs baseline: 1.0725x; 1.0238x over previous
#include <cuda_runtime.h>
#include <cuda_fp16.h>
#include <cstdint>
#include <math.h>

// JAX PRNG scheme: jax_threefry_partitionable=True (verified R2-R14)
#define NPIX   50176            // 224*224
#define IMG    150528           // 3*NPIX
#define BATCH  64
#define NUM_IT 64
#define TOTAL  (BATCH * IMG)
#define NPAIRS 25088            // NPIX/2
#define SIGMA_F 0.05f
#define NSEG   7                 // tile split: 7 segments
#define SEG_PAIRS 3584           // 25088 / 7 = 3584 = 14 * 256 exactly

struct Keys { unsigned int k[2 * NUM_IT]; };

// Scratch (__device__ globals — sanctioned no-allocation path)
__device__ float g_logits_part[NSEG][(NUM_IT + 1) * BATCH];
__device__ float g_d[NUM_IT * BATCH];
__device__ float g_coef[BATCH];
// Interleaved per-pair operands: 8 floats {b0x,b0y,b1x,b1y,b2x,b2y,0,0}
__device__ float4 g_bt[(size_t)BATCH * NPAIRS * 2];   // 51.4 MB
__device__ float4 g_wt[(size_t)NPAIRS * 2];           // 0.8 MB
// Normalized noise as half2(ch0, ch1) per pixel; ch2 = -(ch0+ch1). 822 MB.
__device__ unsigned int g_tn_h[(size_t)NUM_IT * BATCH * NPIX];

typedef unsigned long long u64;

// ---------------------------------------------------------------------------
// f32x2 packed helpers (sm_10x)
// ---------------------------------------------------------------------------
__device__ __forceinline__ u64 pk2(float a, float b) {
    u64 r; asm("mov.b64 %0,{%1,%2};" : "=l"(r) : "f"(a), "f"(b)); return r;
}
__device__ __forceinline__ void upk2(u64 v, float &a, float &b) {
    asm("mov.b64 {%0,%1},%2;" : "=f"(a), "=f"(b) : "l"(v));
}
__device__ __forceinline__ u64 fma2(u64 a, u64 b, u64 c) {
    u64 r; asm("fma.rn.f32x2 %0,%1,%2,%3;" : "=l"(r) : "l"(a), "l"(b), "l"(c)); return r;
}
__device__ __forceinline__ u64 add2(u64 a, u64 b) {
    u64 r; asm("add.rn.f32x2 %0,%1,%2;" : "=l"(r) : "l"(a), "l"(b)); return r;
}
__device__ __forceinline__ u64 mul2(u64 a, u64 b) {
    u64 r; asm("mul.rn.f32x2 %0,%1,%2;" : "=l"(r) : "l"(a), "l"(b)); return r;
}
__device__ __forceinline__ u64 sp2(float a) { return pk2(a, a); }

// scalar add with saturation to [0,1] in ONE FADD (fma pipe)
__device__ __forceinline__ float addsat(float a, float b) {
    float r; asm("add.rn.sat.f32 %0,%1,%2;" : "=f"(r) : "f"(a), "f"(b)); return r;
}
__device__ __forceinline__ float sat(float a) {
    float r; asm("add.rn.sat.f32 %0,%1,0f00000000;" : "=f"(r) : "f"(a)); return r;
}

// ---------------------------------------------------------------------------
// Host-side Threefry-2x32 (key derivation only)
// ---------------------------------------------------------------------------
static void tf2x32_host(unsigned int k0, unsigned int k1,
                        unsigned int x0, unsigned int x1,
                        unsigned int &o0, unsigned int &o1)
{
    unsigned int k2 = k0 ^ k1 ^ 0x1BD11BDAu;
    x0 += k0; x1 += k1;
#define TF_R(r) { x0 += x1; x1 = (x1 << (r)) | (x1 >> (32 - (r))); x1 ^= x0; }
    TF_R(13) TF_R(15) TF_R(26) TF_R(6)
    x0 += k1; x1 += k2 + 1u;
    TF_R(17) TF_R(29) TF_R(16) TF_R(24)
    x0 += k2; x1 += k0 + 2u;
    TF_R(13) TF_R(15) TF_R(26) TF_R(6)
    x0 += k0; x1 += k1 + 3u;
    TF_R(17) TF_R(29) TF_R(16) TF_R(24)
    x0 += k1; x1 += k2 + 4u;
    TF_R(13) TF_R(15) TF_R(26) TF_R(6)
    x0 += k2; x1 += k0 + 5u;
#undef TF_R
    o0 = x0; o1 = x1;
}

// ---------------------------------------------------------------------------
// Integer ops pinned to the fma pipe (IMAD/IMAD.HI) via opaque `one`
// ---------------------------------------------------------------------------
__device__ __forceinline__ unsigned int madd(unsigned int a, unsigned int one,
                                             unsigned int b)
{
    unsigned int r;
    asm("mad.lo.u32 %0, %1, %2, %3;" : "=r"(r) : "r"(a), "r"(one), "r"(b));
    return r;
}
__device__ __forceinline__ unsigned int madhi(unsigned int a, unsigned int b,
                                              unsigned int c)
{
    unsigned int r;
    asm("mad.hi.u32 %0, %1, %2, %3;" : "=r"(r) : "r"(a), "r"(b), "r"(c));
    return r;
}

// Threefry-2x32, counter (0, j), partitionable output x0^x1.  (R10 exact.)
__device__ __forceinline__ unsigned int rbits_m(
    unsigned int k0, unsigned int k1, unsigned int k2,
    unsigned int j, unsigned int one)
{
    unsigned int x0 = k0;                    // counter hi = 0
    unsigned int x1 = madd(j, one, k1);      // counter lo = j
#define TF_RM(r) { x0 = madd(x1, one, x0); \
                   x1 = (x1 << (r)) | (x1 >> (32 - (r))); x1 ^= x0; }
    TF_RM(13) TF_RM(15) TF_RM(26) TF_RM(6)
    x0 = madd(x0, one, k1); x1 = madd(x1, one, k2 + 1u);
    TF_RM(17) TF_RM(29) TF_RM(16) TF_RM(24)
    x0 = madd(x0, one, k2); x1 = madd(x1, one, k0 + 2u);
    TF_RM(13) TF_RM(15) TF_RM(26) TF_RM(6)
    x0 = madd(x0, one, k0); x1 = madd(x1, one, k1 + 3u);
    TF_RM(17) TF_RM(29) TF_RM(16) TF_RM(24)
    x0 = madd(x0, one, k1); x1 = madd(x1, one, k2 + 4u);
    TF_RM(13) TF_RM(15) TF_RM(26) TF_RM(6)
    x0 = madd(x0, one, k2); x1 = madd(x1, one, k0 + 5u);
#undef TF_RM
    return x0 ^ x1;
}

// Tail fixup (w >= 5): XLA's Giles tail polynomial, scalar, inline, rare.
__device__ __forceinline__ float tail_fix(float w, float x)
{
    float s = sqrtf(w) - 3.0f;
    float p =          -0.000200214257f;
    p = fmaf(p, s, 0.000100950558f);
    p = fmaf(p, s, 0.00134934322f);
    p = fmaf(p, s, -0.00367342844f);
    p = fmaf(p, s, 0.00573950773f);
    p = fmaf(p, s, -0.0076224613f);
    p = fmaf(p, s, 0.00943887047f);
    p = fmaf(p, s, 1.00167406f);
    p = fmaf(p, s, 2.83297682f);
    return p * x;
}

// Packed normals (erfinv/sqrt2-scaled); ln2 scale and -2.5 shift folded into
// transformed Giles coefficients, Horner variable zz = log2(1-u^2) + 2.5/ln2.
__device__ __forceinline__ u64 normal2(unsigned int ba, unsigned int bb)
{
    // (bits>>9)|0x3f800000 == mad.hi(bits, 1<<23, 0x3f800000)  (fma pipe)
    unsigned int ia = madhi(ba, 0x00800000u, 0x3f800000u);
    unsigned int ib = madhi(bb, 0x00800000u, 0x3f800000u);
    u64 v = pk2(__uint_as_float(ia), __uint_as_float(ib));
    u64 f = add2(v, sp2(-1.0f));                       // exact (Sterbenz)
    u64 u = fma2(f, sp2(2.0f), sp2(-0.99999994f));     // uniform in [lo,1)
    u64 s = fma2(u, u, sp2(-1.0f));                    // u^2-1 = -(1-u^2)
    float sa_, sb_; upk2(s, sa_, sb_);
    float za = __log2f(-sa_);                          // log2(1-u^2) <= 0
    float zb = __log2f(-sb_);
    u64 zz = add2(pk2(za, zb), sp2(3.6067376f));       // + 2.5/ln2

    u64 p = sp2(1.49742e-9f);                          // e8
    p = fma2(p, zz, sp2(-2.63893e-8f));                // e7
    p = fma2(p, zz, sp2(-3.90762e-7f));                // e6
    p = fma2(p, zz, sp2(7.02653e-7f));                 // e5
    p = fma2(p, zz, sp2(5.045614e-5f));                // e4
    p = fma2(p, zz, sp2(4.1752126e-4f));               // e3
    p = fma2(p, zz, sp2(-2.00718e-3f));                // e2
    p = fma2(p, zz, sp2(-0.17095832f));                // e1
    p = fma2(p, zz, sp2(1.50140941f));                 // e0
    u64 r = mul2(p, u);

    float zza, zzb; upk2(zz, zza, zzb);
    if (zza <= -3.6067376f || zzb <= -3.6067376f) {    // ~20% warp trigger
        float ra, rb, ua_, ub_;
        upk2(r, ra, rb); upk2(u, ua_, ub_);
        if (zza <= -3.6067376f)
            ra = tail_fix(fmaf(-0.6931472f, zza, 2.5f), ua_);
        if (zzb <= -3.6067376f)
            rb = tail_fix(fmaf(-0.6931472f, zzb, 2.5f), ub_);
        r = pk2(ra, rb);
    }
    return r;
}

// ---------------------------------------------------------------------------
// K0a: build interleaved per-pair base records (imgs + noise, transposed)
// ---------------------------------------------------------------------------
__global__ void __launch_bounds__(256) k_base(
    const float* __restrict__ imgs, const float* __restrict__ noise)
{
    int idx = blockIdx.x * 256 + threadIdx.x;        // 64*25088 = 1605632
    int b = idx / NPAIRS;
    int q = idx - b * NPAIRS;
    int j0 = b * IMG + 2 * q;
    const float2 i0 = *reinterpret_cast<const float2*>(imgs + j0);
    const float2 i1 = *reinterpret_cast<const float2*>(imgs + j0 + NPIX);
    const float2 i2 = *reinterpret_cast<const float2*>(imgs + j0 + 2*NPIX);
    const float2 n0 = *reinterpret_cast<const float2*>(noise + j0);
    const float2 n1 = *reinterpret_cast<const float2*>(noise + j0 + NPIX);
    const float2 n2 = *reinterpret_cast<const float2*>(noise + j0 + 2*NPIX);
    float4 lo, hi;
    lo.x = i0.x + n0.x;  lo.y = i0.y + n0.y;
    lo.z = i1.x + n1.x;  lo.w = i1.y + n1.y;
    hi.x = i2.x + n2.x;  hi.y = i2.y + n2.y;
    hi.z = 0.0f; hi.w = 0.0f;
    g_bt[(size_t)idx * 2]     = lo;
    g_bt[(size_t)idx * 2 + 1] = hi;
}

// K0b: same interleave for w (pair-major, batch-independent)
__global__ void __launch_bounds__(256) k_wt(const float* __restrict__ w)
{
    int q = blockIdx.x * 256 + threadIdx.x;          // 25088
    int p = 2 * q;
    const float2 w0 = *reinterpret_cast<const float2*>(w + p);
    const float2 w1 = *reinterpret_cast<const float2*>(w + p + NPIX);
    const float2 w2 = *reinterpret_cast<const float2*>(w + p + 2*NPIX);
    float4 lo, hi;
    lo.x = w0.x; lo.y = w0.y; lo.z = w1.x; lo.w = w1.y;
    hi.x = w2.x; hi.y = w2.y; hi.z = 0.0f; hi.w = 0.0f;
    g_wt[(size_t)q * 2]     = lo;
    g_wt[(size_t)q * 2 + 1] = hi;
}

// ---------------------------------------------------------------------------
// K1: grid (NSEG, BATCH, NUM_IT+1). Each block: one 1/7 pixel segment of one
// (iter, image) tile: exactly 14 loop iters (3584 pairs = 14*256).
// Operand loads are 4x LDG.128 per pair (interleaved records).  (R14 exact.)
// ---------------------------------------------------------------------------
__global__ void __launch_bounds__(256, 8) k_logits(Keys keys, unsigned int one)
{
    const int seg = blockIdx.x;          // pixel segment: 0..6
    const int b   = blockIdx.y;
    const int it  = blockIdx.z;
    const int tid = threadIdx.x;
    const int base = b * IMG;
    const int qbeg = seg * SEG_PAIRS + tid;
    const int qend = (seg + 1) * SEG_PAIRS;
    const float4* __restrict__ btp = g_bt + (size_t)b * NPAIRS * 2;

    float acc = 0.0f;
    if (it < NUM_IT) {
        const unsigned int k0 = keys.k[2 * it], k1 = keys.k[2 * it + 1];
        const unsigned int k2 = k0 ^ k1 ^ 0x1BD11BDAu;
        unsigned int* __restrict__ tdst = g_tn_h + ((size_t)it * BATCH + b) * NPIX;
        #pragma unroll 1
        for (int q = qbeg; q < qend; q += 256) {
            const int p  = 2 * q;
            const int j0 = base + p;
            // 6 hashes: 2 pixels x 3 channels
            u64 t0 = normal2(rbits_m(k0,k1,k2,(unsigned)j0,           one),
                             rbits_m(k0,k1,k2,(unsigned)(j0+1),       one));
            u64 t1 = normal2(rbits_m(k0,k1,k2,(unsigned)(j0+NPIX),    one),
                             rbits_m(k0,k1,k2,(unsigned)(j0+NPIX+1),  one));
            u64 t2 = normal2(rbits_m(k0,k1,k2,(unsigned)(j0+2*NPIX),  one),
                             rbits_m(k0,k1,k2,(unsigned)(j0+2*NPIX+1),one));
            // channel normalization, packed across the pixel pair
            u64 sum   = add2(add2(t0, t1), t2);
            u64 negmu = mul2(sum, sp2(-1.0f / 3.0f));
            u64 d0 = add2(t0, negmu), d1 = add2(t1, negmu), d2 = add2(t2, negmu);
            u64 var = mul2(d0, d0);
            var = fma2(d1, d1, var);
            var = fma2(d2, d2, var);                   // = 2 * var(ddof=1)
            // sc = sigma*sqrt(2)/sqrt(2var) = rsqrt(2var * 200)
            u64 varK = mul2(var, sp2(200.0f));
            float va_, vb_; upk2(varK, va_, vb_);
            u64 sc = pk2(rsqrtf(va_), rsqrtf(vb_));
            u64 tn0 = mul2(d0, sc), tn1 = mul2(d1, sc), tn2 = mul2(d2, sc);

            // store half2(ch0, ch1) per pixel as one STG.64 for the pair
            float x0a, x0b, x1a, x1b;
            upk2(tn0, x0a, x0b); upk2(tn1, x1a, x1b);
            __half2 hA = __floats2half2_rn(x0a, x1a);
            __half2 hB = __floats2half2_rn(x0b, x1b);
            uint2 st;
            st.x = *reinterpret_cast<unsigned int*>(&hA);
            st.y = *reinterpret_cast<unsigned int*>(&hB);
            *reinterpret_cast<uint2*>(tdst + p) = st;

            // dot: 4x LDG.128 interleaved operands, clip folded into FADD.SAT
            float x2a, x2b; upk2(tn2, x2a, x2b);
            const float4 bl = btp[(size_t)q * 2];
            const float4 bh = btp[(size_t)q * 2 + 1];
            const float4 wl = g_wt[(size_t)q * 2];
            const float4 wh = g_wt[(size_t)q * 2 + 1];
            acc = fmaf(addsat(bl.x, x0a), wl.x, acc);
            acc = fmaf(addsat(bl.y, x0b), wl.y, acc);
            acc = fmaf(addsat(bl.z, x1a), wl.z, acc);
            acc = fmaf(addsat(bl.w, x1b), wl.w, acc);
            acc = fmaf(addsat(bh.x, x2a), wh.x, acc);
            acc = fmaf(addsat(bh.y, x2b), wh.y, acc);
        }
    } else {
        #pragma unroll 1
        for (int q = qbeg; q < qend; q += 256) {
            const float4 bl = btp[(size_t)q * 2];
            const float4 bh = btp[(size_t)q * 2 + 1];
            const float4 wl = g_wt[(size_t)q * 2];
            const float4 wh = g_wt[(size_t)q * 2 + 1];
            acc = fmaf(sat(bl.x), wl.x, acc);
            acc = fmaf(sat(bl.y), wl.y, acc);
            acc = fmaf(sat(bl.z), wl.z, acc);
            acc = fmaf(sat(bl.w), wl.w, acc);
            acc = fmaf(sat(bh.x), wh.x, acc);
            acc = fmaf(sat(bh.y), wh.y, acc);
        }
    }

    __shared__ float red[256];
    red[tid] = acc;
    __syncthreads();
    #pragma unroll
    for (int s = 128; s > 32; s >>= 1) {
        if (tid < s) red[tid] += red[tid + s];
        __syncthreads();
    }
    if (tid < 32) {
        float v = red[tid] + red[tid + 32];
        #pragma unroll
        for (int o = 16; o > 0; o >>= 1)
            v += __shfl_down_sync(0xFFFFFFFFu, v, o);
        if (tid == 0) g_logits_part[seg][it * BATCH + b] = v;
    }
}

// ---------------------------------------------------------------------------
// K2: parallel — grid(BATCH) blocks x 64 threads (one per iteration).
// Each thread: its iteration's logit + d; block-reduce nc; thread 0: coef.
// ---------------------------------------------------------------------------
__global__ void __launch_bounds__(64) k_dvals(const float* __restrict__ b_dnet)
{
    const int b = blockIdx.x;
    const int i = threadIdx.x;           // iteration 0..63
    float bb = b_dnet[0];

    // baseline logit (redundant per thread; 7 broadcast loads)
    float l2 = 0.0f;
    #pragma unroll
    for (int s = 0; s < NSEG; s++) l2 += g_logits_part[s][NUM_IT * BATCH + b];
    float p2 = 1.0f / (1.0f + expf(-(l2 + bb)));

    float li = 0.0f;
    #pragma unroll
    for (int s = 0; s < NSEG; s++) li += g_logits_part[s][i * BATCH + b];
    float pi = 1.0f / (1.0f + expf(-(li + bb)));
    float d = p2 - pi;
    g_d[i * BATCH + b] = d;

    // block reduction of d^2 over 64 threads (2 warps)
    float v = d * d;
    #pragma unroll
    for (int o = 16; o > 0; o >>= 1)
        v += __shfl_down_sync(0xFFFFFFFFu, v, o);
    __shared__ float part[2];
    if ((i & 31) == 0) part[i >> 5] = v;
    __syncthreads();
    if (i == 0) {
        float nc = part[0] + part[1];
        g_coef[b] = 1.0f / ((float)NUM_IT * (sqrtf(nc) + 1e-10f) * SIGMA_F);
    }
}

// ---------------------------------------------------------------------------
// K3: per-pixel output; stream precomputed half2 tn (822 MB read, DRAM-bound)
// ---------------------------------------------------------------------------
__global__ void __launch_bounds__(256) k_output(float* __restrict__ out)
{
    __shared__ float dsh[NUM_IT];
    const int b = blockIdx.y;
    if (threadIdx.x < NUM_IT) dsh[threadIdx.x] = g_d[threadIdx.x * BATCH + b];
    __syncthreads();

    const int p = blockIdx.x * 256 + threadIdx.x;
    const size_t stride = (size_t)BATCH * NPIX;
    const unsigned int* __restrict__ tp = g_tn_h + (size_t)b * NPIX + p;

    float a0 = 0.0f, a1 = 0.0f, a2 = 0.0f;
    #pragma unroll 8
    for (int i = 0; i < NUM_IT; i++) {
        unsigned int hb = tp[i * stride];
        __half2 h = *reinterpret_cast<__half2*>(&hb);
        float2 tn = __half22float2(h);
        float di = dsh[i];
        a0 = fmaf(tn.x, di, a0);
        a1 = fmaf(tn.y, di, a1);
        a2 = fmaf(-(tn.x + tn.y), di, a2);
    }
    float c = g_coef[b];
    const int j0 = b * IMG + p;
    out[j0]            = a0 * c;
    out[j0 + NPIX]     = a1 * c;
    out[j0 + 2 * NPIX] = a2 * c;
}

// ---------------------------------------------------------------------------
extern "C" void kernel_launch(void* const* d_in, const int* in_sizes, int n_in,
                              void* d_out, int out_size)
{
    const float* imgs  = (const float*)d_in[0];
    const float* noise = (const float*)d_in[1];
    const float* w     = (const float*)d_in[2];
    const float* bb    = (const float*)d_in[3];
    float* out = (float*)d_out;

    // keys = jax.random.split(jax.random.key(42), 64); base key data (0, 42)
    Keys keys;
    for (int i = 0; i < NUM_IT; i++) {
        unsigned int o0, o1;
        tf2x32_host(0u, 42u, 0u, (unsigned)i, o0, o1);
        keys.k[2 * i] = o0; keys.k[2 * i + 1] = o1;
    }

    k_base<<<(BATCH * NPAIRS) / 256, 256>>>(imgs, noise);  // 6272 blocks
    k_wt<<<NPAIRS / 256, 256>>>(w);                        // 98 blocks

    dim3 g1(NSEG, BATCH, NUM_IT + 1);   // 7 x 64 x 65 = 29120 blocks
    k_logits<<<g1, 256>>>(keys, 1u);

    k_dvals<<<BATCH, 64>>>(bb);

    dim3 g3(NPIX / 256, BATCH);   // 50176 = 196 * 256 exactly
    k_output<<<g3, 256>>>(out);
}